// round 12
// baseline (speedup 1.0000x reference)
#include <cuda_runtime.h>
#include <cuda_fp16.h>
#include <cstdint>

#define NN 20000
#define CC 64
#define II 16
#define KK2 120
#define KK1 8
#define KK0 4

#define TPC 4
#define NS 10                  // k16 steps (K = 160)
#define QSW 84                 // Q row stride in words (336 B = 21*16B, odd 16B units)
#define SQW (128 * QSW)        // 10752 words
#define SFW 2560               // sF: 128 rows x 20 floats
#define SMEM_BYTES ((SQW + SFW) * 4)   // 53248

// device scratch
__device__ float    g_W2[CC * 4096];        // [c][x*256+y*16+i]
__device__ uint32_t g_VfragH[CC * 32 * 40]; // per-lane fp16x2 B fragments

// ---------------- helpers ----------------
struct PYI { int y, i; };
__host__ __device__ constexpr PYI pairOf(int p) {
    int y = 0, c = 16;
    while (p >= c) { p -= c; ++y; --c; }
    return {y, y + p};
}

__device__ __forceinline__ uint32_t packh2(float lo, float hi) {
    __half2 h = __floats2half2_rn(lo, hi);
    return *(uint32_t*)&h;
}
__device__ __forceinline__ void mma16816(float (&d)[4], uint32_t a0, uint32_t a1,
                                         uint32_t a2, uint32_t a3, uint32_t b0,
                                         uint32_t b1) {
    asm volatile(
        "mma.sync.aligned.m16n8k16.row.col.f32.f16.f16.f32 "
        "{%0,%1,%2,%3},{%4,%5,%6,%7},{%8,%9},{%0,%1,%2,%3};"
        : "+f"(d[0]), "+f"(d[1]), "+f"(d[2]), "+f"(d[3])
        : "r"(a0), "r"(a1), "r"(a2), "r"(a3), "r"(b0), "r"(b1));
}
__device__ __forceinline__ void ldmx4(uint32_t& a0, uint32_t& a1, uint32_t& a2,
                                      uint32_t& a3, unsigned addr) {
    asm volatile("ldmatrix.sync.aligned.m8n8.x4.shared.b16 {%0,%1,%2,%3}, [%4];"
                 : "=r"(a0), "=r"(a1), "=r"(a2), "=r"(a3) : "r"(addr));
}

// feature value (plain k-index): 0=const, 1..16=f, 17..152=sym pairs, rest 0
template <int Q>
__device__ __forceinline__ float qv(const float (&f)[16]) {
    if constexpr (Q == 0) return 1.0f;
    else if constexpr (Q <= 16) return f[Q - 1];
    else if constexpr (Q < 153) {
        constexpr PYI pr = pairOf(Q - 17);
        return f[pr.y] * f[pr.i];
    } else return 0.0f;
}

// build half a Q row (80 halfs, natural k order), KB = 80*H
template <int CH, int KB>
__device__ __forceinline__ void buildQn(const float (&f)[16], unsigned ad) {
    if constexpr (CH < NS) {
        constexpr int B = KB + 8 * CH;
        uint32_t w0 = packh2(qv<B + 0>(f), qv<B + 1>(f));
        uint32_t w1 = packh2(qv<B + 2>(f), qv<B + 3>(f));
        uint32_t w2 = packh2(qv<B + 4>(f), qv<B + 5>(f));
        uint32_t w3 = packh2(qv<B + 6>(f), qv<B + 7>(f));
        asm volatile("st.shared.v4.b32 [%0], {%1,%2,%3,%4};"
                     :: "r"(ad + CH * 16), "r"(w0), "r"(w1), "r"(w2), "r"(w3)
                     : "memory");
        buildQn<CH + 1, KB>(f, ad);
    }
}

// ---------------- precompute 1: W2 = U2 . w2 (128 blocks x 32 rows) ----------------
__global__ void __launch_bounds__(256) precompW2(const float* __restrict__ U2,
                                                 const float* __restrict__ w2) {
    __shared__ float sw[KK2 * CC];   // 30720 B
    __shared__ float su[32 * KK2];   // 15360 B
    int t = threadIdx.x;
    {   // vectorized staging (float4, high MLP)
        const float4* w4 = (const float4*)w2;
        float4* sw4 = (float4*)sw;
#pragma unroll 4
        for (int j = t; j < KK2 * CC / 4; j += 256) sw4[j] = w4[j];
        const float4* u4 = (const float4*)(U2 + (size_t)blockIdx.x * 32 * KK2);
        float4* su4 = (float4*)su;
#pragma unroll 2
        for (int j = t; j < 32 * KK2 / 4; j += 256) su4[j] = u4[j];
    }
    __syncthreads();

    int lr = t >> 4, cg = t & 15;   // rows lr, lr+16; channels cg*4..+3
    float a[8];
#pragma unroll
    for (int q = 0; q < 8; q++) a[q] = 0.f;
    const float* u0p = &su[lr * KK2];
    const float* u1p = &su[(lr + 16) * KK2];
#pragma unroll 4
    for (int k = 0; k < KK2; k++) {
        float u0 = u0p[k], u1 = u1p[k];
        float4 w = *(const float4*)&sw[k * CC + cg * 4];
        a[0] = fmaf(u0, w.x, a[0]); a[1] = fmaf(u0, w.y, a[1]);
        a[2] = fmaf(u0, w.z, a[2]); a[3] = fmaf(u0, w.w, a[3]);
        a[4] = fmaf(u1, w.x, a[4]); a[5] = fmaf(u1, w.y, a[5]);
        a[6] = fmaf(u1, w.z, a[6]); a[7] = fmaf(u1, w.w, a[7]);
    }
    int r0 = blockIdx.x * 32;
#pragma unroll
    for (int q = 0; q < 4; q++) {
        g_W2[(size_t)(cg * 4 + q) * 4096 + r0 + lr]      = a[q];
        g_W2[(size_t)(cg * 4 + q) * 4096 + r0 + lr + 16] = a[4 + q];
    }
}

// ---------------- precompute 2: per-lane fp16 B fragments ----------------
__device__ __forceinline__ float vvalS(int c, int x, int q, const float* sW,
                                       const float* U1, const float* w1,
                                       const float* U0, const float* w0) {
    float acc = 0.f;
    if (q == 0) {
#pragma unroll
        for (int k = 0; k < KK0; k++)
            acc = fmaf(U0[x * KK0 + k], w0[k * CC + c], acc);
    } else if (q <= 16) {
        int y = q - 1;
#pragma unroll
        for (int k = 0; k < KK1; k++)
            acc = fmaf(U1[(x * II + y) * KK1 + k], w1[k * CC + c], acc);
    } else if (q < 153) {
        int p = q - 17, y = 0, cnt = 16;
        while (p >= cnt) { p -= cnt; ++y; --cnt; }
        int i = y + p;
        acc = sW[x * 256 + y * 16 + i];
        if (i != y) acc += sW[x * 256 + i * 16 + y];
    }
    return acc;
}

__global__ void __launch_bounds__(256) precompVfrag(const float* __restrict__ U1,
                                                    const float* __restrict__ w1,
                                                    const float* __restrict__ U0,
                                                    const float* __restrict__ w0) {
    __shared__ float sW[4096];   // W2[c] tile, 16 KB
    int c = blockIdx.x >> 1;
    int half = blockIdx.x & 1;
    int t = threadIdx.x;
    {
        const float4* g4 = (const float4*)(g_W2 + (size_t)c * 4096);
        float4* s4 = (float4*)sW;
#pragma unroll
        for (int j = t; j < 1024; j += 256) s4[j] = g4[j];
    }
    __syncthreads();

    for (int idx = half * 640 + t; idx < half * 640 + 640; idx += 256) {
        int wq = idx & 3;
        int s = (idx >> 2) % NS;
        int lane = idx / 40;
        int g = lane >> 2, tg = lane & 3;
        int x = g + (wq >> 1) * 8;
        int kb = s * 16 + 2 * tg + (wq & 1) * 8;
        float vA = vvalS(c, x, kb,     sW, U1, w1, U0, w0);
        float vB = vvalS(c, x, kb + 1, sW, U1, w1, U0, w0);
        g_VfragH[(size_t)c * 1280 + idx] = packh2(vA, vB);
    }
}

// ---------------- main kernel ----------------
__global__ void __launch_bounds__(256, 2) contract_mma(const float* __restrict__ nf,
                                                       float* __restrict__ out) {
    extern __shared__ float sm[];
    float* sF = sm + SQW;
    unsigned sqb = (unsigned)__cvta_generic_to_shared(sm);
    int tid = threadIdx.x;
    int lane = tid & 31, w = tid >> 5;
    int g = lane >> 2, tg = lane & 3;
    int c = blockIdx.y;

    // B fragments: 10 x uint4 per lane, in registers for CTA lifetime
    uint4 bw[NS];
    const uint4* vp = (const uint4*)(g_VfragH + (size_t)(c * 32 + lane) * 40);
#pragma unroll
    for (int s = 0; s < NS; s++) bw[s] = vp[s];

    // builder mapping: row ab (0..127), half H (warp-uniform)
    int ab = tid & 127, H = tid >> 7;
    unsigned qA = sqb + (unsigned)(ab * QSW) * 4 + H * 160;
    // ldmatrix per-lane address (natural k-order Q)
    unsigned lmb = sqb
        + (unsigned)((16 * w + ((lane >> 3) & 1) * 8 + (lane & 7)) * QSW) * 4
        + ((lane >> 4) & 1) * 16;

    int tbase0 = blockIdx.x * TPC * 128;

    // prefetch tile 0 row f (each builder loads its own row; 2x L1-broadcast)
    float4 pf0 = {0,0,0,0}, pf1 = pf0, pf2 = pf0, pf3 = pf0;
    {
        int n = tbase0 + ab;
        if (n < NN) {
            const float4* p = (const float4*)(nf + ((size_t)n * CC + c) * II);
            pf0 = p[0]; pf1 = p[1]; pf2 = p[2]; pf3 = p[3];
        }
    }

    for (int t = 0; t < TPC; t++) {
        int base = tbase0 + t * 128;
        if (base >= NN) break;

        float f[16] = {pf0.x, pf0.y, pf0.z, pf0.w, pf1.x, pf1.y, pf1.z, pf1.w,
                       pf2.x, pf2.y, pf2.z, pf2.w, pf3.x, pf3.y, pf3.z, pf3.w};

        // H=0 half also stages exact fp32 f for the epilogue
        if (H == 0) {
            *(float4*)&sF[ab * 20 + 0]  = pf0;
            *(float4*)&sF[ab * 20 + 4]  = pf1;
            *(float4*)&sF[ab * 20 + 8]  = pf2;
            *(float4*)&sF[ab * 20 + 12] = pf3;
        }

        // build fp16 Q half-row (compile-time k, warp-uniform H)
        if (H == 0) buildQn<0, 0>(f, qA);
        else        buildQn<0, 80>(f, qA);
        __syncthreads();

        // prefetch next tile's row
        pf0 = make_float4(0,0,0,0); pf1 = pf0; pf2 = pf0; pf3 = pf0;
        if (t + 1 < TPC) {
            int n = base + 128 + ab;
            if (n < NN) {
                const float4* p = (const float4*)(nf + ((size_t)n * CC + c) * II);
                pf0 = p[0]; pf1 = p[1]; pf2 = p[2]; pf3 = p[3];
            }
        }

        // MMA: warp w handles rows 16w..16w+15 via ldmatrix
        float dA[4] = {0, 0, 0, 0}, dB[4] = {0, 0, 0, 0};
#pragma unroll
        for (int s = 0; s < NS; s++) {
            uint32_t a0, a1, a2, a3;
            ldmx4(a0, a1, a2, a3, lmb + s * 32);
            mma16816(dA, a0, a1, a2, a3, bw[s].x, bw[s].y);
            mma16816(dB, a0, a1, a2, a3, bw[s].z, bw[s].w);
        }

        // epilogue: out = sum_x t[x] * f[x] (exact fp32 f from sF)
#pragma unroll
        for (int h = 0; h < 2; h++) {
            int r = 16 * w + g + h * 8;
            float2 fa = *(const float2*)&sF[r * 20 + 2 * tg];
            float2 fb = *(const float2*)&sF[r * 20 + 8 + 2 * tg];
            float p = dA[h * 2] * fa.x + dA[h * 2 + 1] * fa.y
                    + dB[h * 2] * fb.x + dB[h * 2 + 1] * fb.y;
            p += __shfl_xor_sync(0xffffffffu, p, 1);
            p += __shfl_xor_sync(0xffffffffu, p, 2);
            int atom = base + r;
            if (tg == 0 && atom < NN) out[(size_t)atom * CC + c] = p;
        }
        __syncthreads();
    }
}

extern "C" void kernel_launch(void* const* d_in, const int* in_sizes, int n_in,
                              void* d_out, int out_size) {
    const float* nf = (const float*)d_in[0];
    const float* U2 = (const float*)d_in[1];
    const float* U1 = (const float*)d_in[2];
    const float* U0 = (const float*)d_in[3];
    const float* w2 = (const float*)d_in[4];
    const float* w1 = (const float*)d_in[5];
    const float* w0 = (const float*)d_in[6];
    float* out = (float*)d_out;

    cudaFuncSetAttribute(contract_mma, cudaFuncAttributeMaxDynamicSharedMemorySize,
                         SMEM_BYTES);

    precompW2<<<128, 256>>>(U2, w2);
    precompVfrag<<<128, 256>>>(U1, w1, U0, w0);

    dim3 grid(40, CC);
    contract_mma<<<grid, 256, SMEM_BYTES>>>(nf, out);
}

// round 13
// speedup vs baseline: 1.1898x; 1.1898x over previous
#include <cuda_runtime.h>
#include <cuda_fp16.h>
#include <cstdint>

#define NN 20000
#define CC 64
#define II 16
#define KK2 120
#define KK1 8
#define KK0 4

#define TPC 4
#define NS 10                 // k16 steps (K = 160)
#define QSTRIDE 88            // Q row stride in 32-bit words
#define SQW 11264             // Q region size in words
#define SFW 2560              // sF: 128 rows x 20 floats
#define SMEM_BYTES ((SQW + SFW) * 4)   // 55296

// device scratch
__device__ float    g_W2[CC * 4096];        // [c][x*256+y*16+i]
__device__ uint32_t g_VfragH[CC * 32 * 40]; // per-lane fp16x2 B fragments

// ---------------- helpers ----------------
struct PYI { int y, i; };
__host__ __device__ constexpr PYI pairOf(int p) {
    int y = 0, c = 16;
    while (p >= c) { p -= c; ++y; --c; }
    return {y, y + p};
}

__device__ __forceinline__ uint32_t packh2(float lo, float hi) {
    __half2 h = __floats2half2_rn(lo, hi);
    return *(uint32_t*)&h;
}
__device__ __forceinline__ void ldsv2(uint32_t& a, uint32_t& b, unsigned addr) {
    asm volatile("ld.shared.v2.b32 {%0,%1}, [%2];" : "=r"(a), "=r"(b) : "r"(addr));
}
__device__ __forceinline__ void mma16816(float (&d)[4], uint32_t a0, uint32_t a1,
                                         uint32_t a2, uint32_t a3, uint32_t b0,
                                         uint32_t b1) {
    asm volatile(
        "mma.sync.aligned.m16n8k16.row.col.f32.f16.f16.f32 "
        "{%0,%1,%2,%3},{%4,%5,%6,%7},{%8,%9},{%0,%1,%2,%3};"
        : "+f"(d[0]), "+f"(d[1]), "+f"(d[2]), "+f"(d[3])
        : "r"(a0), "r"(a1), "r"(a2), "r"(a3), "r"(b0), "r"(b1));
}

// feature value (plain k-index): 0=const, 1..16=f, 17..152=sym pairs, rest 0
template <int Q>
__device__ __forceinline__ float qv(const float (&f)[16]) {
    if constexpr (Q == 0) return 1.0f;
    else if constexpr (Q <= 16) return f[Q - 1];
    else if constexpr (Q < 153) {
        constexpr PYI pr = pairOf(Q - 17);
        return f[pr.y] * f[pr.i];
    } else return 0.0f;
}

// build 10 fp16 chunks for one row half (H warp-uniform).
// chunk (s,H): k-base B = 16s+4H, words = (B,B+1)(B+8,B+9)(B+2,B+3)(B+10,B+11)
template <int CH, int H>
__device__ __forceinline__ void buildQ(const float (&f)[16], unsigned wb) {
    if constexpr (CH < NS) {
        constexpr int B = 16 * CH + 4 * H;
        uint32_t w0 = packh2(qv<B + 0>(f),  qv<B + 1>(f));
        uint32_t w1 = packh2(qv<B + 8>(f),  qv<B + 9>(f));
        uint32_t w2 = packh2(qv<B + 2>(f),  qv<B + 3>(f));
        uint32_t w3 = packh2(qv<B + 10>(f), qv<B + 11>(f));
        asm volatile("st.shared.v4.b32 [%0], {%1,%2,%3,%4};"
                     :: "r"(wb + CH * 32), "r"(w0), "r"(w1), "r"(w2), "r"(w3)
                     : "memory");
        buildQ<CH + 1, H>(f, wb);
    }
}

// ---------------- precompute 1: W2 = U2 . w2 (256 blocks x 16 rows) ----------------
__global__ void __launch_bounds__(256) precompW2(const float* __restrict__ U2,
                                                 const float* __restrict__ w2) {
    __shared__ float sw[KK2 * CC];   // 30720 B
    __shared__ float su[16 * KK2];   // 7680 B
    int t = threadIdx.x;
    {   // vectorized staging (float4, high MLP)
        const float4* w4 = (const float4*)w2;
        float4* sw4 = (float4*)sw;
#pragma unroll 4
        for (int j = t; j < KK2 * CC / 4; j += 256) sw4[j] = w4[j];
        const float4* u4 = (const float4*)(U2 + (size_t)blockIdx.x * 16 * KK2);
        float4* su4 = (float4*)su;
#pragma unroll 2
        for (int j = t; j < 16 * KK2 / 4; j += 256) su4[j] = u4[j];
    }
    __syncthreads();

    int lr = t >> 4, cg = t & 15;   // row lr (0..15); channels cg*4..+3
    float a0 = 0.f, a1 = 0.f, a2 = 0.f, a3 = 0.f;
    const float* up = &su[lr * KK2];
#pragma unroll 4
    for (int k = 0; k < KK2; k++) {
        float u = up[k];
        float4 w = *(const float4*)&sw[k * CC + cg * 4];
        a0 = fmaf(u, w.x, a0); a1 = fmaf(u, w.y, a1);
        a2 = fmaf(u, w.z, a2); a3 = fmaf(u, w.w, a3);
    }
    int r = blockIdx.x * 16 + lr;
    g_W2[(size_t)(cg * 4 + 0) * 4096 + r] = a0;
    g_W2[(size_t)(cg * 4 + 1) * 4096 + r] = a1;
    g_W2[(size_t)(cg * 4 + 2) * 4096 + r] = a2;
    g_W2[(size_t)(cg * 4 + 3) * 4096 + r] = a3;
}

// ---------------- precompute 2: per-lane fp16 B fragments ----------------
__device__ __forceinline__ float vvalS(int c, int x, int q, const float* sW,
                                       const float* U1, const float* w1,
                                       const float* U0, const float* w0) {
    float acc = 0.f;
    if (q == 0) {
#pragma unroll
        for (int k = 0; k < KK0; k++)
            acc = fmaf(U0[x * KK0 + k], w0[k * CC + c], acc);
    } else if (q <= 16) {
        int y = q - 1;
#pragma unroll
        for (int k = 0; k < KK1; k++)
            acc = fmaf(U1[(x * II + y) * KK1 + k], w1[k * CC + c], acc);
    } else if (q < 153) {
        int p = q - 17, y = 0, cnt = 16;
        while (p >= cnt) { p -= cnt; ++y; --cnt; }
        int i = y + p;
        acc = sW[x * 256 + y * 16 + i];
        if (i != y) acc += sW[x * 256 + i * 16 + y];
    }
    return acc;
}

__global__ void __launch_bounds__(256) precompVfrag(const float* __restrict__ U1,
                                                    const float* __restrict__ w1,
                                                    const float* __restrict__ U0,
                                                    const float* __restrict__ w0) {
    __shared__ float sW[4096];   // W2[c] tile, 16 KB
    int c = blockIdx.x >> 1;
    int half = blockIdx.x & 1;
    int t = threadIdx.x;
    {
        const float4* g4 = (const float4*)(g_W2 + (size_t)c * 4096);
        float4* s4 = (float4*)sW;
#pragma unroll
        for (int j = t; j < 1024; j += 256) s4[j] = g4[j];
    }
    __syncthreads();

    for (int idx = half * 640 + t; idx < half * 640 + 640; idx += 256) {
        int wq = idx & 3;
        int s = (idx >> 2) % NS;
        int lane = idx / 40;
        int g = lane >> 2, tg = lane & 3;
        int x = g + (wq >> 1) * 8;
        int kb = s * 16 + 2 * tg + (wq & 1) * 8;
        float vA = vvalS(c, x, kb,     sW, U1, w1, U0, w0);
        float vB = vvalS(c, x, kb + 1, sW, U1, w1, U0, w0);
        g_VfragH[(size_t)c * 1280 + idx] = packh2(vA, vB);
    }
}

// ---------------- main kernel (round-9 design, best measured) ----------------
__global__ void __launch_bounds__(256, 2) contract_mma(const float* __restrict__ nf,
                                                       float* __restrict__ out) {
    extern __shared__ float sm[];
    float* sF = sm + SQW;
    unsigned sqb = (unsigned)__cvta_generic_to_shared(sm);
    int tid = threadIdx.x;
    int lane = tid & 31, w = tid >> 5;
    int g = lane >> 2, tg = lane & 3;
    int c = blockIdx.y;

    // B fragments: 10 x uint4 per lane, in registers for CTA lifetime
    uint4 bw[NS];
    const uint4* vp = (const uint4*)(g_VfragH + (size_t)(c * 32 + lane) * 40);
#pragma unroll
    for (int s = 0; s < NS; s++) bw[s] = vp[s];

    // loader mapping
    int la = tid >> 1, lh = tid & 1;
    // builder mapping (warp-uniform half)
    int ab = tid & 127, H = tid >> 7;
    unsigned wbq = sqb + (unsigned)(ab * QSTRIDE + ((ab >> 2) & 1) * 4 + H * 4) * 4;
    // MMA A addresses
    unsigned aA = sqb + (unsigned)((16 * w + g) * QSTRIDE + ((g >> 2) & 1) * 4
                                   + tg * 2) * 4;

    int tbase0 = blockIdx.x * TPC * 128;
    float4 pv0 = {0, 0, 0, 0}, pv1 = pv0;
    {
        int n = tbase0 + la;
        if (n < NN) {
            const float4* p = (const float4*)(nf + ((size_t)n * CC + c) * II + lh * 8);
            pv0 = p[0]; pv1 = p[1];
        }
    }

    for (int t = 0; t < TPC; t++) {
        int base = tbase0 + t * 128;
        if (base >= NN) break;

        // stage exact fp32 f
        *(float4*)&sF[la * 20 + lh * 8]     = pv0;
        *(float4*)&sF[la * 20 + lh * 8 + 4] = pv1;
        __syncthreads();

        // build fp16 Q (half row per thread, warp-uniform H)
        {
            float f[16];
            float4 c0 = *(float4*)&sF[ab * 20 + 0];
            float4 c1 = *(float4*)&sF[ab * 20 + 4];
            float4 c2 = *(float4*)&sF[ab * 20 + 8];
            float4 c3 = *(float4*)&sF[ab * 20 + 12];
            f[0] = c0.x; f[1] = c0.y; f[2] = c0.z; f[3] = c0.w;
            f[4] = c1.x; f[5] = c1.y; f[6] = c1.z; f[7] = c1.w;
            f[8] = c2.x; f[9] = c2.y; f[10] = c2.z; f[11] = c2.w;
            f[12] = c3.x; f[13] = c3.y; f[14] = c3.z; f[15] = c3.w;
            if (H == 0) buildQ<0, 0>(f, wbq);
            else        buildQ<0, 1>(f, wbq);
        }
        __syncthreads();

        // prefetch next tile's f
        pv0 = make_float4(0, 0, 0, 0); pv1 = pv0;
        if (t + 1 < TPC) {
            int n = base + 128 + la;
            if (n < NN) {
                const float4* p =
                    (const float4*)(nf + ((size_t)n * CC + c) * II + lh * 8);
                pv0 = p[0]; pv1 = p[1];
            }
        }

        // MMA: warp w handles rows 16w..16w+15
        float dA[4] = {0, 0, 0, 0}, dB[4] = {0, 0, 0, 0};
#pragma unroll
        for (int s = 0; s < NS; s++) {
            uint32_t a0, a2, a1, a3;
            ldsv2(a0, a2, aA + s * 32);
            ldsv2(a1, a3, aA + s * 32 + 8 * QSTRIDE * 4);
            mma16816(dA, a0, a1, a2, a3, bw[s].x, bw[s].y);
            mma16816(dB, a0, a1, a2, a3, bw[s].z, bw[s].w);
        }

        // epilogue: out = sum_x t[x] * f[x] (exact fp32 f)
#pragma unroll
        for (int h = 0; h < 2; h++) {
            int r = 16 * w + g + h * 8;
            float2 fa = *(const float2*)&sF[r * 20 + 2 * tg];
            float2 fb = *(const float2*)&sF[r * 20 + 8 + 2 * tg];
            float p = dA[h * 2] * fa.x + dA[h * 2 + 1] * fa.y
                    + dB[h * 2] * fb.x + dB[h * 2 + 1] * fb.y;
            p += __shfl_xor_sync(0xffffffffu, p, 1);
            p += __shfl_xor_sync(0xffffffffu, p, 2);
            int atom = base + r;
            if (tg == 0 && atom < NN) out[(size_t)atom * CC + c] = p;
        }
        __syncthreads();
    }
}

extern "C" void kernel_launch(void* const* d_in, const int* in_sizes, int n_in,
                              void* d_out, int out_size) {
    const float* nf = (const float*)d_in[0];
    const float* U2 = (const float*)d_in[1];
    const float* U1 = (const float*)d_in[2];
    const float* U0 = (const float*)d_in[3];
    const float* w2 = (const float*)d_in[4];
    const float* w1 = (const float*)d_in[5];
    const float* w0 = (const float*)d_in[6];
    float* out = (float*)d_out;

    cudaFuncSetAttribute(contract_mma, cudaFuncAttributeMaxDynamicSharedMemorySize,
                         SMEM_BYTES);

    precompW2<<<256, 256>>>(U2, w2);
    precompVfrag<<<128, 256>>>(U1, w1, U0, w0);

    dim3 grid(40, CC);
    contract_mma<<<grid, 256, SMEM_BYTES>>>(nf, out);
}

// round 14
// speedup vs baseline: 1.2126x; 1.0192x over previous
#include <cuda_runtime.h>
#include <cuda_fp16.h>
#include <cstdint>

#define NN 20000
#define CC 64
#define II 16
#define KK2 120
#define KK1 8
#define KK0 4

#define TPC 4
#define NS 10                 // k16 steps (K = 160)
#define QSTRIDE 88            // Q row stride in 32-bit words
#define SQW 11264             // Q region size in words
#define SFW 2560              // sF: 128 rows x 20 floats
#define SMEM_BYTES ((SQW + SFW) * 4)   // 55296

// device scratch
__device__ float    g_W2[CC * 4096];        // [c][x*256+y*16+i]
__device__ uint32_t g_VfragH[CC * 32 * 40]; // per-lane fp16x2 B fragments

// ---------------- helpers ----------------
struct PYI { int y, i; };
__host__ __device__ constexpr PYI pairOf(int p) {
    int y = 0, c = 16;
    while (p >= c) { p -= c; ++y; --c; }
    return {y, y + p};
}

__device__ __forceinline__ uint32_t packh2(float lo, float hi) {
    __half2 h = __floats2half2_rn(lo, hi);
    return *(uint32_t*)&h;
}
__device__ __forceinline__ void ldsv2(uint32_t& a, uint32_t& b, unsigned addr) {
    asm volatile("ld.shared.v2.b32 {%0,%1}, [%2];" : "=r"(a), "=r"(b) : "r"(addr));
}
__device__ __forceinline__ void mma16816(float (&d)[4], uint32_t a0, uint32_t a1,
                                         uint32_t a2, uint32_t a3, uint32_t b0,
                                         uint32_t b1) {
    asm volatile(
        "mma.sync.aligned.m16n8k16.row.col.f32.f16.f16.f32 "
        "{%0,%1,%2,%3},{%4,%5,%6,%7},{%8,%9},{%0,%1,%2,%3};"
        : "+f"(d[0]), "+f"(d[1]), "+f"(d[2]), "+f"(d[3])
        : "r"(a0), "r"(a1), "r"(a2), "r"(a3), "r"(b0), "r"(b1));
}

// feature value (plain k-index): 0=const, 1..16=f, 17..152=sym pairs, rest 0
template <int Q>
__device__ __forceinline__ float qv(const float (&f)[16]) {
    if constexpr (Q == 0) return 1.0f;
    else if constexpr (Q <= 16) return f[Q - 1];
    else if constexpr (Q < 153) {
        constexpr PYI pr = pairOf(Q - 17);
        return f[pr.y] * f[pr.i];
    } else return 0.0f;
}

// build 10 fp16 chunks for one row half.
// chunk (s,H): k-base B = 16s+4H, words = (B,B+1)(B+8,B+9)(B+2,B+3)(B+10,B+11)
template <int CH, int H>
__device__ __forceinline__ void buildQ(const float (&f)[16], unsigned wb) {
    if constexpr (CH < NS) {
        constexpr int B = 16 * CH + 4 * H;
        uint32_t w0 = packh2(qv<B + 0>(f),  qv<B + 1>(f));
        uint32_t w1 = packh2(qv<B + 8>(f),  qv<B + 9>(f));
        uint32_t w2 = packh2(qv<B + 2>(f),  qv<B + 3>(f));
        uint32_t w3 = packh2(qv<B + 10>(f), qv<B + 11>(f));
        asm volatile("st.shared.v4.b32 [%0], {%1,%2,%3,%4};"
                     :: "r"(wb + CH * 32), "r"(w0), "r"(w1), "r"(w2), "r"(w3)
                     : "memory");
        buildQ<CH + 1, H>(f, wb);
    }
}

// ---------------- precompute 1: W2 = U2 . w2 (256 blocks x 16 rows) ----------------
__global__ void __launch_bounds__(256) precompW2(const float* __restrict__ U2,
                                                 const float* __restrict__ w2) {
    __shared__ float sw[KK2 * CC];   // 30720 B
    __shared__ float su[16 * KK2];   // 7680 B
    int t = threadIdx.x;
    {
        const float4* w4 = (const float4*)w2;
        float4* sw4 = (float4*)sw;
#pragma unroll 4
        for (int j = t; j < KK2 * CC / 4; j += 256) sw4[j] = w4[j];
        const float4* u4 = (const float4*)(U2 + (size_t)blockIdx.x * 16 * KK2);
        float4* su4 = (float4*)su;
#pragma unroll 2
        for (int j = t; j < 16 * KK2 / 4; j += 256) su4[j] = u4[j];
    }
    __syncthreads();

    int lr = t >> 4, cg = t & 15;
    float a0 = 0.f, a1 = 0.f, a2 = 0.f, a3 = 0.f;
    const float* up = &su[lr * KK2];
#pragma unroll 4
    for (int k = 0; k < KK2; k++) {
        float u = up[k];
        float4 w = *(const float4*)&sw[k * CC + cg * 4];
        a0 = fmaf(u, w.x, a0); a1 = fmaf(u, w.y, a1);
        a2 = fmaf(u, w.z, a2); a3 = fmaf(u, w.w, a3);
    }
    int r = blockIdx.x * 16 + lr;
    g_W2[(size_t)(cg * 4 + 0) * 4096 + r] = a0;
    g_W2[(size_t)(cg * 4 + 1) * 4096 + r] = a1;
    g_W2[(size_t)(cg * 4 + 2) * 4096 + r] = a2;
    g_W2[(size_t)(cg * 4 + 3) * 4096 + r] = a3;
}

// ---------------- precompute 2: per-lane fp16 B fragments ----------------
__device__ __forceinline__ float vvalS(int c, int x, int q, const float* sW,
                                       const float* U1, const float* w1,
                                       const float* U0, const float* w0) {
    float acc = 0.f;
    if (q == 0) {
#pragma unroll
        for (int k = 0; k < KK0; k++)
            acc = fmaf(U0[x * KK0 + k], w0[k * CC + c], acc);
    } else if (q <= 16) {
        int y = q - 1;
#pragma unroll
        for (int k = 0; k < KK1; k++)
            acc = fmaf(U1[(x * II + y) * KK1 + k], w1[k * CC + c], acc);
    } else if (q < 153) {
        int p = q - 17, y = 0, cnt = 16;
        while (p >= cnt) { p -= cnt; ++y; --cnt; }
        int i = y + p;
        acc = sW[x * 256 + y * 16 + i];
        if (i != y) acc += sW[x * 256 + i * 16 + y];
    }
    return acc;
}

__global__ void __launch_bounds__(256) precompVfrag(const float* __restrict__ U1,
                                                    const float* __restrict__ w1,
                                                    const float* __restrict__ U0,
                                                    const float* __restrict__ w0) {
    __shared__ float sW[4096];
    int c = blockIdx.x >> 1;
    int half = blockIdx.x & 1;
    int t = threadIdx.x;
    {
        const float4* g4 = (const float4*)(g_W2 + (size_t)c * 4096);
        float4* s4 = (float4*)sW;
#pragma unroll
        for (int j = t; j < 1024; j += 256) s4[j] = g4[j];
    }
    __syncthreads();

    for (int idx = half * 640 + t; idx < half * 640 + 640; idx += 256) {
        int wq = idx & 3;
        int s = (idx >> 2) % NS;
        int lane = idx / 40;
        int g = lane >> 2, tg = lane & 3;
        int x = g + (wq >> 1) * 8;
        int kb = s * 16 + 2 * tg + (wq & 1) * 8;
        float vA = vvalS(c, x, kb,     sW, U1, w1, U0, w0);
        float vB = vvalS(c, x, kb + 1, sW, U1, w1, U0, w0);
        g_VfragH[(size_t)c * 1280 + idx] = packh2(vA, vB);
    }
}

// ---------------- main kernel: 128 threads, occ 4, thread-owns-row ----------------
__global__ void __launch_bounds__(128, 4) contract_mma(const float* __restrict__ nf,
                                                       float* __restrict__ out) {
    extern __shared__ float sm[];
    float* sF = sm + SQW;
    unsigned sqb = (unsigned)__cvta_generic_to_shared(sm);
    int tid = threadIdx.x;
    int lane = tid & 31, w = tid >> 5;
    int g = lane >> 2, tg = lane & 3;
    int c = blockIdx.y;

    // B fragments: 10 x uint4 per lane (same for all warps)
    uint4 bw[NS];
    const uint4* vp = (const uint4*)(g_VfragH + (size_t)(c * 32 + lane) * 40);
#pragma unroll
    for (int s = 0; s < NS; s++) bw[s] = vp[s];

    // own-row Q write base (round-9 row swizzle)
    unsigned wbq = sqb + (unsigned)(tid * QSTRIDE + ((tid >> 2) & 1) * 4) * 4;
    // MMA A addresses for the warp's two m-tiles (rows 32w+16mt+g)
    unsigned aA0 = sqb + (unsigned)((32 * w + g) * QSTRIDE + ((g >> 2) & 1) * 4
                                    + tg * 2) * 4;
    unsigned aA1 = aA0 + 16 * QSTRIDE * 4;
    const unsigned rowskip = 8 * QSTRIDE * 4;

    int tbase0 = blockIdx.x * TPC * 128;

    // prefetch tile 0: own row
    float4 pf0 = {0,0,0,0}, pf1 = pf0, pf2 = pf0, pf3 = pf0;
    {
        int n = tbase0 + tid;
        if (n < NN) {
            const float4* p = (const float4*)(nf + ((size_t)n * CC + c) * II);
            pf0 = p[0]; pf1 = p[1]; pf2 = p[2]; pf3 = p[3];
        }
    }

    for (int t = 0; t < TPC; t++) {
        int base = tbase0 + t * 128;
        if (base >= NN) break;

        float f[16] = {pf0.x, pf0.y, pf0.z, pf0.w, pf1.x, pf1.y, pf1.z, pf1.w,
                       pf2.x, pf2.y, pf2.z, pf2.w, pf3.x, pf3.y, pf3.z, pf3.w};

        // stage exact fp32 f (own row)
        *(float4*)&sF[tid * 20 + 0]  = pf0;
        *(float4*)&sF[tid * 20 + 4]  = pf1;
        *(float4*)&sF[tid * 20 + 8]  = pf2;
        *(float4*)&sF[tid * 20 + 12] = pf3;

        // build full fp16 Q row (both halves)
        buildQ<0, 0>(f, wbq);
        buildQ<0, 1>(f, wbq + 16);
        __syncthreads();

        // prefetch next tile's row
        pf0 = make_float4(0,0,0,0); pf1 = pf0; pf2 = pf0; pf3 = pf0;
        if (t + 1 < TPC) {
            int n = base + 128 + tid;
            if (n < NN) {
                const float4* p = (const float4*)(nf + ((size_t)n * CC + c) * II);
                pf0 = p[0]; pf1 = p[1]; pf2 = p[2]; pf3 = p[3];
            }
        }

        // MMA: warp w covers rows 32w..32w+31 as two m16 tiles, 4 chains
        float dA0[4] = {0,0,0,0}, dB0[4] = {0,0,0,0};
        float dA1[4] = {0,0,0,0}, dB1[4] = {0,0,0,0};
#pragma unroll
        for (int s = 0; s < NS; s++) {
            uint32_t a0, a1, a2, a3;
            ldsv2(a0, a2, aA0 + s * 32);
            ldsv2(a1, a3, aA0 + s * 32 + rowskip);
            mma16816(dA0, a0, a1, a2, a3, bw[s].x, bw[s].y);
            mma16816(dB0, a0, a1, a2, a3, bw[s].z, bw[s].w);
            uint32_t b0, b1, b2, b3;
            ldsv2(b0, b2, aA1 + s * 32);
            ldsv2(b1, b3, aA1 + s * 32 + rowskip);
            mma16816(dA1, b0, b1, b2, b3, bw[s].x, bw[s].y);
            mma16816(dB1, b0, b1, b2, b3, bw[s].z, bw[s].w);
        }

        // epilogue: out = sum_x t[x] * f[x] (exact fp32 f from sF)
#pragma unroll
        for (int mt = 0; mt < 2; mt++) {
            const float* dA = mt ? dA1 : dA0;
            const float* dB = mt ? dB1 : dB0;
#pragma unroll
            for (int h = 0; h < 2; h++) {
                int r = 32 * w + 16 * mt + g + h * 8;
                float2 fa = *(const float2*)&sF[r * 20 + 2 * tg];
                float2 fb = *(const float2*)&sF[r * 20 + 8 + 2 * tg];
                float p = dA[h * 2] * fa.x + dA[h * 2 + 1] * fa.y
                        + dB[h * 2] * fb.x + dB[h * 2 + 1] * fb.y;
                p += __shfl_xor_sync(0xffffffffu, p, 1);
                p += __shfl_xor_sync(0xffffffffu, p, 2);
                int atom = base + r;
                if (tg == 0 && atom < NN) out[(size_t)atom * CC + c] = p;
            }
        }
        __syncthreads();
    }
}

extern "C" void kernel_launch(void* const* d_in, const int* in_sizes, int n_in,
                              void* d_out, int out_size) {
    const float* nf = (const float*)d_in[0];
    const float* U2 = (const float*)d_in[1];
    const float* U1 = (const float*)d_in[2];
    const float* U0 = (const float*)d_in[3];
    const float* w2 = (const float*)d_in[4];
    const float* w1 = (const float*)d_in[5];
    const float* w0 = (const float*)d_in[6];
    float* out = (float*)d_out;

    cudaFuncSetAttribute(contract_mma, cudaFuncAttributeMaxDynamicSharedMemorySize,
                         SMEM_BYTES);

    precompW2<<<256, 256>>>(U2, w2);
    precompVfrag<<<128, 256>>>(U1, w1, U0, w0);

    dim3 grid(40, CC);
    contract_mma<<<grid, 128, SMEM_BYTES>>>(nf, out);
}